// round 16
// baseline (speedup 1.0000x reference)
#include <cuda_runtime.h>
#include <cuda_fp16.h>
#include <math.h>
#include <stdint.h>

#define NN   50000
#define EE   800000
#define DD   256
#define HH   256
#define BB   64
#define LL   32
#define SCAN_NB 196            // 196 * 256 = 50176 >= NN

typedef unsigned long long ull;

// ---------------- scratch (static device globals; no allocation) ----------------
__device__ int    g_degI[NN];
__device__ int    g_rowptr[NN + 1];
__device__ int    g_cursor[NN];
__device__ int    g_bsums[256];
__device__ int    g_esrc[EE];
__device__ unsigned g_bar;
__device__ __half g_x16[(size_t)NN * DD];
__device__ __half g_agg16[(size_t)NN * DD];
__device__ __half g_h16[(size_t)NN * HH];
__device__ __half g_emb16[(size_t)NN * HH];
__device__ __half g_wt1[256 * 512];          // [n][k] fp16 fused (w1l ; w1r)
__device__ __half g_wt2[256 * 512];
__device__ __half g_wih16[1024 * 256];       // [n][k] fp16
__device__ float  g_emb[(size_t)NN * HH];
__device__ float  g_gsum[BB * HH];
__device__ float  g_gcnt[BB];
__device__ float  g_whhT[HH * 4 * HH];
__device__ float  g_bsum[4 * HH];
__device__ float  g_xw[(size_t)BB * LL * 4 * HH];
__device__ float  g_hl0[BB * HH];
__device__ float  g_hl1[BB * HH];

// ---------------- helpers ----------------
__device__ __forceinline__ float sigf(float x) { return 1.f / (1.f + __expf(-x)); }

__device__ __forceinline__ uint32_t s2u(const void* p) {
    uint32_t a;
    asm("{ .reg .u64 t; cvta.to.shared.u64 t, %1; cvt.u32.u64 %0, t; }" : "=r"(a) : "l"(p));
    return a;
}
__device__ __forceinline__ void cpa16(void* dst, const void* src) {
    uint32_t d = s2u(dst);
    asm volatile("cp.async.cg.shared.global [%0], [%1], 16;" :: "r"(d), "l"(src));
}
__device__ __forceinline__ void mma_f16(float* c, const uint32_t* a, const uint32_t* b) {
    asm volatile("mma.sync.aligned.m16n8k16.row.col.f32.f16.f16.f32 "
                 "{%0,%1,%2,%3}, {%4,%5,%6,%7}, {%8,%9}, {%0,%1,%2,%3};"
                 : "+f"(c[0]), "+f"(c[1]), "+f"(c[2]), "+f"(c[3])
                 : "r"(a[0]), "r"(a[1]), "r"(a[2]), "r"(a[3]), "r"(b[0]), "r"(b[1]));
}
__device__ __forceinline__ void ldsm4(uint32_t& r0, uint32_t& r1, uint32_t& r2, uint32_t& r3,
                                      uint32_t addr) {
    asm volatile("ldmatrix.sync.aligned.m8n8.x4.shared.b16 {%0,%1,%2,%3}, [%4];"
                 : "=r"(r0), "=r"(r1), "=r"(r2), "=r"(r3) : "r"(addr));
}
__device__ __forceinline__ void cpa_wait(int n) {
    if (n >= 2)      asm volatile("cp.async.wait_group 2;" ::: "memory");
    else if (n == 1) asm volatile("cp.async.wait_group 1;" ::: "memory");
    else             asm volatile("cp.async.wait_group 0;" ::: "memory");
}

// ---------------- fused front: cvt x->fp16, deg count, graph count ----------------
__global__ void k_front(const float2* __restrict__ x, __half2* __restrict__ x16,
                        const int* __restrict__ dst, int* __restrict__ degI,
                        const int* __restrict__ batch, float* __restrict__ gcnt,
                        int E, int N) {
    int i = blockIdx.x * blockDim.x + threadIdx.x;
    if (i < N * DD / 2) x16[i] = __float22half2_rn(x[i]);
    if (i < E) atomicAdd(&degI[dst[i]], 1);
    if (i < N) atomicAdd(&gcnt[batch[i]], 1.f);
}

// ---------------- scan (3-phase) ----------------
__global__ __launch_bounds__(256) void k_scanA(const int* __restrict__ degI,
                                               int* __restrict__ bsums) {
    __shared__ int red[256];
    int t = threadIdx.x;
    int idx = blockIdx.x * 256 + t;
    red[t] = (idx < NN) ? degI[idx] : 0;
    __syncthreads();
    for (int off = 128; off > 0; off >>= 1) {
        if (t < off) red[t] += red[t + off];
        __syncthreads();
    }
    if (t == 0) bsums[blockIdx.x] = red[0];
}
__global__ __launch_bounds__(256) void k_scanB(int* __restrict__ bsums,
                                               int* __restrict__ rowptr) {
    __shared__ int sc[256];
    int t = threadIdx.x;
    int v = (t < SCAN_NB) ? bsums[t] : 0;
    sc[t] = v;
    __syncthreads();
    for (int off = 1; off < 256; off <<= 1) {
        int u = (t >= off) ? sc[t - off] : 0;
        __syncthreads();
        sc[t] += u;
        __syncthreads();
    }
    if (t < SCAN_NB) bsums[t] = sc[t] - v;
    if (t == SCAN_NB - 1) rowptr[NN] = sc[t];
}
__global__ __launch_bounds__(256) void k_scanC(const int* __restrict__ degI,
                                               const int* __restrict__ bsums,
                                               int* __restrict__ rowptr,
                                               int* __restrict__ cursor) {
    __shared__ int sc[256];
    int t = threadIdx.x;
    int idx = blockIdx.x * 256 + t;
    int v = (idx < NN) ? degI[idx] : 0;
    sc[t] = v;
    __syncthreads();
    for (int off = 1; off < 256; off <<= 1) {
        int u = (t >= off) ? sc[t - off] : 0;
        __syncthreads();
        sc[t] += u;
        __syncthreads();
    }
    if (idx < NN) {
        int ex = sc[t] - v + bsums[blockIdx.x];
        rowptr[idx] = ex;
        cursor[idx] = ex;
    }
}

__global__ void k_fill(const int* __restrict__ src, const int* __restrict__ dst,
                       int* __restrict__ cursor, int* __restrict__ esrc, int E) {
    int e = blockIdx.x * blockDim.x + threadIdx.x;
    if (e < E) {
        int d = dst[e];
        int pos = atomicAdd(&cursor[d], 1);
        esrc[pos] = src[e];
    }
}

// ---------------- fused weight prep ----------------
__global__ void k_prep_all(const float* __restrict__ w1l, const float* __restrict__ w1r,
                           const float* __restrict__ w2l, const float* __restrict__ w2r,
                           const float* __restrict__ w_ih, const float* __restrict__ w_hh,
                           const float* __restrict__ b_ih, const float* __restrict__ b_hh,
                           __half* __restrict__ wt1, __half* __restrict__ wt2,
                           __half* __restrict__ wih16, float* __restrict__ whhT,
                           float* __restrict__ bsum) {
    int idx = blockIdx.x * blockDim.x + threadIdx.x;
    if (idx < 4 * HH * HH) {
        int n = idx >> 8, k = idx & 255;
        whhT[k * 1024 + n] = w_hh[idx];
        wih16[idx] = __float2half_rn(w_ih[idx]);
    }
    if (idx < 131072) {
        int n = idx >> 9, k = idx & 511;
        float v1 = (k < 256) ? w1l[k * 256 + n] : w1r[(k - 256) * 256 + n];
        float v2 = (k < 256) ? w2l[k * 256 + n] : w2r[(k - 256) * 256 + n];
        wt1[n * 512 + k] = __float2half_rn(v1);
        wt2[n * 512 + k] = __float2half_rn(v2);
    }
    if (idx < 4 * HH) bsum[idx] = b_ih[idx] + b_hh[idx];
}

// ---------------- fp16 CSR gather (4-edge unrolled for MLP) ----------------
__device__ __forceinline__ void accum_row(float* acc, uint4 v) {
    float2 f0 = __half22float2(*(__half2*)&v.x);
    float2 f1 = __half22float2(*(__half2*)&v.y);
    float2 f2 = __half22float2(*(__half2*)&v.z);
    float2 f3 = __half22float2(*(__half2*)&v.w);
    acc[0] += f0.x; acc[1] += f0.y; acc[2] += f1.x; acc[3] += f1.y;
    acc[4] += f2.x; acc[5] += f2.y; acc[6] += f3.x; acc[7] += f3.y;
}

__global__ __launch_bounds__(256) void k_gather_h(const uint4* __restrict__ x16,
                                                  const int* __restrict__ rowptr,
                                                  const int* __restrict__ esrc,
                                                  uint4* __restrict__ agg16, int N) {
    int node = blockIdx.x * 8 + (threadIdx.x >> 5);
    int lane = threadIdx.x & 31;
    if (node >= N) return;
    int s = rowptr[node], e = rowptr[node + 1];
    float acc[8] = {0.f, 0.f, 0.f, 0.f, 0.f, 0.f, 0.f, 0.f};
    int i = s;
    for (; i + 3 < e; i += 4) {
        int s0 = __ldg(&esrc[i]),     s1 = __ldg(&esrc[i + 1]);
        int s2 = __ldg(&esrc[i + 2]), s3 = __ldg(&esrc[i + 3]);
        uint4 v0 = x16[(size_t)s0 * 32 + lane];
        uint4 v1 = x16[(size_t)s1 * 32 + lane];
        uint4 v2 = x16[(size_t)s2 * 32 + lane];
        uint4 v3 = x16[(size_t)s3 * 32 + lane];
        accum_row(acc, v0);
        accum_row(acc, v1);
        accum_row(acc, v2);
        accum_row(acc, v3);
    }
    for (; i + 1 < e; i += 2) {
        int s0 = __ldg(&esrc[i]), s1 = __ldg(&esrc[i + 1]);
        uint4 v0 = x16[(size_t)s0 * 32 + lane];
        uint4 v1 = x16[(size_t)s1 * 32 + lane];
        accum_row(acc, v0);
        accum_row(acc, v1);
    }
    if (i < e) {
        int s0 = __ldg(&esrc[i]);
        uint4 v0 = x16[(size_t)s0 * 32 + lane];
        accum_row(acc, v0);
    }
    float inv = 1.f / fmaxf((float)(e - s), 1.f);
    uint4 o;
    *(__half2*)&o.x = __floats2half2_rn(acc[0] * inv, acc[1] * inv);
    *(__half2*)&o.y = __floats2half2_rn(acc[2] * inv, acc[3] * inv);
    *(__half2*)&o.z = __floats2half2_rn(acc[4] * inv, acc[5] * inv);
    *(__half2*)&o.w = __floats2half2_rn(acc[6] * inv, acc[7] * inv);
    agg16[(size_t)node * 32 + lane] = o;
}

// ---------------- fp16 mma node GEMM (fused K=512, 4-stage pipeline) -----------
#define HPAD 40
#define HA_SZ (128 * HPAD * 2)
#define HB_SZ (256 * HPAD * 2)
#define HSTAGE (HA_SZ + HB_SZ)             // 30720
#define HMMA_SMEM (4 * HSTAGE)             // 122880

__global__ __launch_bounds__(512) void k_gemm_h(
    const __half* __restrict__ A1, const __half* __restrict__ A2,
    const __half* __restrict__ W, const float* __restrict__ bias,
    __half* __restrict__ Ch, float* __restrict__ Cf, int M, int relu)
{
    extern __shared__ char sm_[];
    const int tid = threadIdx.x;
    const int wid = tid >> 5, lane = tid & 31;
    const int warpM = (wid & 3) * 32, warpN = (wid >> 2) * 64;
    const int bm = blockIdx.x * 128;
    const int grp = lane >> 2, qid = lane & 3;
    const int lane8 = lane & 7;
    const int aRow = ((lane >> 3) & 1) * 8 + lane8;
    const int aK   = (lane >> 4) * 8;
    const int bRow = (lane >> 4) * 8 + lane8;
    const int bK   = ((lane >> 3) & 1) * 8;

    float c[2][8][4];
#pragma unroll
    for (int mt = 0; mt < 2; mt++)
#pragma unroll
        for (int nt = 0; nt < 8; nt++)
#pragma unroll
            for (int j = 0; j < 4; j++) c[mt][nt][j] = 0.f;

    auto loadChunk = [&](int kc) {
        const __half* A = (kc < 8) ? A1 : A2;
        int k0 = (kc & 7) * 32;
        char* stage = sm_ + (kc & 3) * HSTAGE;
        __half* Ab = (__half*)stage;
        __half* Bb = (__half*)(stage + HA_SZ);
        {
            int r = tid >> 2, c16 = tid & 3;
            int gr = bm + r; if (gr >= M) gr = 0;
            cpa16(Ab + r * HPAD + c16 * 8, A + (size_t)gr * 256 + k0 + c16 * 8);
        }
#pragma unroll
        for (int it = 0; it < 2; it++) {
            int idx = tid + it * 512;
            int n = idx >> 2, c16 = idx & 3;
            cpa16(Bb + n * HPAD + c16 * 8, W + (size_t)n * 512 + kc * 32 + c16 * 8);
        }
        asm volatile("cp.async.commit_group;" ::: "memory");
    };

    loadChunk(0);
    loadChunk(1);
    loadChunk(2);

    for (int kc = 0; kc < 16; kc++) {
        cpa_wait(15 - kc);
        __syncthreads();                 // all threads done reading stage (kc+3)&3
        if (kc + 3 < 16) loadChunk(kc + 3);
        const char* stage = sm_ + (kc & 3) * HSTAGE;
        const uint32_t AbU = s2u(stage);
        const uint32_t BbU = s2u(stage + HA_SZ);
#pragma unroll
        for (int kst = 0; kst < 2; kst++) {
            uint32_t af[2][4];
#pragma unroll
            for (int mt = 0; mt < 2; mt++)
                ldsm4(af[mt][0], af[mt][1], af[mt][2], af[mt][3],
                      AbU + (uint32_t)(((warpM + mt * 16 + aRow) * HPAD + kst * 16 + aK) * 2));
            uint32_t bf[8][2];
#pragma unroll
            for (int p = 0; p < 4; p++)
                ldsm4(bf[2 * p][0], bf[2 * p][1], bf[2 * p + 1][0], bf[2 * p + 1][1],
                      BbU + (uint32_t)(((warpN + p * 16 + bRow) * HPAD + kst * 16 + bK) * 2));
#pragma unroll
            for (int mt = 0; mt < 2; mt++)
#pragma unroll
                for (int nt = 0; nt < 8; nt++)
                    mma_f16(c[mt][nt], af[mt], bf[nt]);
        }
    }

#pragma unroll
    for (int mt = 0; mt < 2; mt++) {
        int r0 = bm + warpM + mt * 16 + grp;
        int r1 = r0 + 8;
#pragma unroll
        for (int nt = 0; nt < 8; nt++) {
            int col = warpN + nt * 8 + qid * 2;
            float b0 = bias[col], b1 = bias[col + 1];
            float v00 = c[mt][nt][0] + b0, v01 = c[mt][nt][1] + b1;
            float v10 = c[mt][nt][2] + b0, v11 = c[mt][nt][3] + b1;
            if (relu) {
                v00 = fmaxf(v00, 0.f); v01 = fmaxf(v01, 0.f);
                v10 = fmaxf(v10, 0.f); v11 = fmaxf(v11, 0.f);
            }
            if (Ch) {
                if (r0 < M) *(__half2*)(Ch + (size_t)r0 * 256 + col) = __floats2half2_rn(v00, v01);
                if (r1 < M) *(__half2*)(Ch + (size_t)r1 * 256 + col) = __floats2half2_rn(v10, v11);
            }
            if (Cf) {
                if (r0 < M) *(float2*)(Cf + (size_t)r0 * 256 + col) = make_float2(v00, v01);
                if (r1 < M) *(float2*)(Cf + (size_t)r1 * 256 + col) = make_float2(v10, v11);
            }
        }
    }
}

// ---------------- fp16 mma xw GEMM (gathered A, K=256, N=1024, 4-stage) --------
__global__ __launch_bounds__(512) void k_gemm_hx(
    const __half* __restrict__ emb16, const int* __restrict__ paths,
    const __half* __restrict__ W, const float* __restrict__ bsum,
    float* __restrict__ xw, int M)
{
    extern __shared__ char sm_[];
    const int tid = threadIdx.x;
    const int wid = tid >> 5, lane = tid & 31;
    const int warpM = (wid & 3) * 32, warpN = (wid >> 2) * 64;
    const int bm = blockIdx.x * 128;
    const int n0g = blockIdx.y * 256;
    const int grp = lane >> 2, qid = lane & 3;
    const int lane8 = lane & 7;
    const int aRow = ((lane >> 3) & 1) * 8 + lane8;
    const int aK   = (lane >> 4) * 8;
    const int bRow = (lane >> 4) * 8 + lane8;
    const int bK   = ((lane >> 3) & 1) * 8;

    float c[2][8][4];
#pragma unroll
    for (int mt = 0; mt < 2; mt++)
#pragma unroll
        for (int nt = 0; nt < 8; nt++)
#pragma unroll
            for (int j = 0; j < 4; j++) c[mt][nt][j] = 0.f;

    auto loadChunk = [&](int kc) {
        int k0 = kc * 32;
        char* stage = sm_ + (kc & 3) * HSTAGE;
        __half* Ab = (__half*)stage;
        __half* Bb = (__half*)(stage + HA_SZ);
        {
            int r = tid >> 2, c16 = tid & 3;
            int gr = __ldg(&paths[bm + r]);
            cpa16(Ab + r * HPAD + c16 * 8, emb16 + (size_t)gr * 256 + k0 + c16 * 8);
        }
#pragma unroll
        for (int it = 0; it < 2; it++) {
            int idx = tid + it * 512;
            int n = idx >> 2, c16 = idx & 3;
            cpa16(Bb + n * HPAD + c16 * 8, W + (size_t)(n0g + n) * 256 + k0 + c16 * 8);
        }
        asm volatile("cp.async.commit_group;" ::: "memory");
    };

    loadChunk(0);
    loadChunk(1);
    loadChunk(2);

    for (int kc = 0; kc < 8; kc++) {
        cpa_wait(7 - kc);
        __syncthreads();
        if (kc + 3 < 8) loadChunk(kc + 3);
        const char* stage = sm_ + (kc & 3) * HSTAGE;
        const uint32_t AbU = s2u(stage);
        const uint32_t BbU = s2u(stage + HA_SZ);
#pragma unroll
        for (int kst = 0; kst < 2; kst++) {
            uint32_t af[2][4];
#pragma unroll
            for (int mt = 0; mt < 2; mt++)
                ldsm4(af[mt][0], af[mt][1], af[mt][2], af[mt][3],
                      AbU + (uint32_t)(((warpM + mt * 16 + aRow) * HPAD + kst * 16 + aK) * 2));
            uint32_t bf[8][2];
#pragma unroll
            for (int p = 0; p < 4; p++)
                ldsm4(bf[2 * p][0], bf[2 * p][1], bf[2 * p + 1][0], bf[2 * p + 1][1],
                      BbU + (uint32_t)(((warpN + p * 16 + bRow) * HPAD + kst * 16 + bK) * 2));
#pragma unroll
            for (int mt = 0; mt < 2; mt++)
#pragma unroll
                for (int nt = 0; nt < 8; nt++)
                    mma_f16(c[mt][nt], af[mt], bf[nt]);
        }
    }

#pragma unroll
    for (int mt = 0; mt < 2; mt++) {
        int r0 = bm + warpM + mt * 16 + grp;
        int r1 = r0 + 8;
#pragma unroll
        for (int nt = 0; nt < 8; nt++) {
            int gcol = n0g + warpN + nt * 8 + qid * 2;
            float b0 = bsum[gcol], b1 = bsum[gcol + 1];
            *(float2*)(xw + (size_t)r0 * 1024 + gcol) =
                make_float2(c[mt][nt][0] + b0, c[mt][nt][1] + b1);
            *(float2*)(xw + (size_t)r1 * 1024 + gcol) =
                make_float2(c[mt][nt][2] + b0, c[mt][nt][3] + b1);
        }
    }
}

// ---------------- pooling over sorted batch ----------------
__global__ void k_pool(const float* __restrict__ emb, const int* __restrict__ batch,
                       float* __restrict__ gsum, int N) {
    __shared__ int bs_[512];
    int n0 = blockIdx.x * 512;
    int cnt = min(512, N - n0);
    for (int i = threadIdx.x; i < cnt; i += 256) bs_[i] = batch[n0 + i];
    __syncthreads();
    int j = threadIdx.x;
    float acc = 0.f;
    int cur = bs_[0];
    for (int i = 0; i < cnt; i++) {
        int b = bs_[i];
        if (b != cur) { atomicAdd(&gsum[cur * 256 + j], acc); acc = 0.f; cur = b; }
        acc += emb[(size_t)(n0 + i) * 256 + j];
    }
    atomicAdd(&gsum[cur * 256 + j], acc);
}

// ---------------- persistent LSTM (scalar, single-poller barrier) --------------
#define LSTM_SMEM (16 * 256 * 4 + 256 * 32 * 4 + 16 * 8 * 4)   // 49664

__global__ __launch_bounds__(256) void k_lstm_all(
    const float* __restrict__ xw, const float* __restrict__ whhT,
    float* __restrict__ h0, float* __restrict__ h1, unsigned* __restrict__ bar)
{
    extern __shared__ char sm_[];
    float (*hs)[256] = (float(*)[256])sm_;
    float (*ws)[32]  = (float(*)[32])(sm_ + 16 * 256 * 4);
    float (*cs)[8]   = (float(*)[8])(sm_ + 16 * 256 * 4 + 256 * 32 * 4);

    const int tid = threadIdx.x;
    const int rt = blockIdx.x, ht = blockIdx.y;
    const int rowBase = rt * 16;

    for (int i = tid; i < 256 * 32; i += 256) {
        int k = i >> 5, gg = i & 31, g = gg >> 3, jj = gg & 7;
        ws[k][gg] = whhT[k * 1024 + g * 256 + ht * 8 + jj];
    }
    if (tid < 128) ((float*)cs)[tid] = 0.f;
    __syncthreads();

    const int gg = tid & 31, rr = tid >> 5;
    const int g = gg >> 3, jj = gg & 7;
    const int gidx = g * 256 + ht * 8 + jj;
    const int hidx = ht * 8 + jj;
    const int row0 = rowBase + rr, row1 = row0 + 8;
    const unsigned fm = 0xffffffffu;

    for (int t = 0; t < LL; t++) {
        const float* hin = (t & 1) ? h1 : h0;
        float* hout = (t & 1) ? h0 : h1;

        if (t == 0) {
            for (int i = tid; i < 16 * 256; i += 256) hs[i >> 8][i & 255] = 0.f;
        } else {
            for (int i = tid; i < 16 * 256; i += 256)
                hs[i >> 8][i & 255] = __ldcg(&hin[(rowBase + (i >> 8)) * 256 + (i & 255)]);
        }
        __syncthreads();

        float acc0 = 0.f, acc1 = 0.f;
#pragma unroll 8
        for (int k = 0; k < 256; k++) {
            float w = ws[k][gg];
            acc0 = fmaf(hs[rr][k], w, acc0);
            acc1 = fmaf(hs[rr + 8][k], w, acc1);
        }
        float v0 = acc0 + xw[(size_t)(row0 * LL + t) * 1024 + gidx];
        float v1 = acc1 + xw[(size_t)(row1 * LL + t) * 1024 + gidx];

        float i0 = __shfl_sync(fm, v0, jj),      f0 = __shfl_sync(fm, v0, 8 + jj);
        float gt0 = __shfl_sync(fm, v0, 16 + jj), o0 = __shfl_sync(fm, v0, 24 + jj);
        float i1 = __shfl_sync(fm, v1, jj),      f1 = __shfl_sync(fm, v1, 8 + jj);
        float gt1 = __shfl_sync(fm, v1, 16 + jj), o1 = __shfl_sync(fm, v1, 24 + jj);

        if (g == 0) {
            float cc0 = cs[rr][jj];
            cc0 = sigf(f0) * cc0 + sigf(i0) * tanhf(gt0);
            cs[rr][jj] = cc0;
            hout[row0 * 256 + hidx] = sigf(o0) * tanhf(cc0);
            float cc1 = cs[rr + 8][jj];
            cc1 = sigf(f1) * cc1 + sigf(i1) * tanhf(gt1);
            cs[rr + 8][jj] = cc1;
            hout[row1 * 256 + hidx] = sigf(o1) * tanhf(cc1);
            __threadfence();
        }
        __syncthreads();

        if (t < LL - 1) {
            if (tid == 0) {
                unsigned target = 128u * (unsigned)(t + 1);
                atomicAdd(bar, 1u);
                while (*(volatile unsigned*)bar < target) { }
            }
            __syncthreads();
        }
    }
}

// ---------------- fused tail: concat + scorer MLP + reduce ----------------
__global__ __launch_bounds__(256) void k_tail(
    const float* __restrict__ gsum, const float* __restrict__ gcnt,
    const float* __restrict__ hfin, const float* __restrict__ wm1,
    const float* __restrict__ bm1, const float* __restrict__ wm2,
    const float* __restrict__ bm2, float* __restrict__ out)
{
    __shared__ float comb[512];
    __shared__ float sred[256];
    int b = blockIdx.x, tid = threadIdx.x;
    float inv = 1.f / fmaxf(gcnt[b], 1.f);
    comb[tid] = gsum[b * 256 + tid] * inv;
    comb[256 + tid] = hfin[b * 256 + tid];
    __syncthreads();
    float acc = bm1[tid];
#pragma unroll 8
    for (int k = 0; k < 512; k++)
        acc = fmaf(comb[k], wm1[k * 256 + tid], acc);
    acc = fmaxf(acc, 0.f);
    sred[tid] = acc * wm2[tid];
    __syncthreads();
    for (int off = 128; off > 0; off >>= 1) {
        if (tid < off) sred[tid] += sred[tid + off];
        __syncthreads();
    }
    if (tid == 0) out[b] = sred[0] + bm2[0];
}

// ---------------- launch ----------------
extern "C" void kernel_launch(void* const* d_in, const int* in_sizes, int n_in,
                              void* d_out, int out_size) {
    const float* x    = (const float*)d_in[0];
    const int*   ei   = (const int*)d_in[1];
    const int*   batch= (const int*)d_in[2];
    const int*   paths= (const int*)d_in[3];
    const float* w1l  = (const float*)d_in[4];
    const float* b1l  = (const float*)d_in[5];
    const float* w1r  = (const float*)d_in[6];
    const float* w2l  = (const float*)d_in[7];
    const float* b2l  = (const float*)d_in[8];
    const float* w2r  = (const float*)d_in[9];
    const float* w_ih = (const float*)d_in[10];
    const float* w_hh = (const float*)d_in[11];
    const float* b_ih = (const float*)d_in[12];
    const float* b_hh = (const float*)d_in[13];
    const float* wm1  = (const float*)d_in[14];
    const float* bm1  = (const float*)d_in[15];
    const float* wm2  = (const float*)d_in[16];
    const float* bm2  = (const float*)d_in[17];
    float* out = (float*)d_out;

    const int N = in_sizes[0] / DD;     // 50000
    const int E = in_sizes[1] / 2;      // 800000
    const int* src = ei;
    const int* dst = ei + E;

    int *degI, *rowptr, *cursor, *bsums, *esrc;
    __half *x16, *agg16, *h16, *emb16, *wt1, *wt2, *wih16;
    float *emb, *gsum, *gcnt, *whhT, *bsum;
    float *xw, *hl0, *hl1;
    unsigned* bar;
    cudaGetSymbolAddress((void**)&degI,   g_degI);
    cudaGetSymbolAddress((void**)&rowptr, g_rowptr);
    cudaGetSymbolAddress((void**)&cursor, g_cursor);
    cudaGetSymbolAddress((void**)&bsums,  g_bsums);
    cudaGetSymbolAddress((void**)&esrc,   g_esrc);
    cudaGetSymbolAddress((void**)&bar,    g_bar);
    cudaGetSymbolAddress((void**)&x16,    g_x16);
    cudaGetSymbolAddress((void**)&agg16,  g_agg16);
    cudaGetSymbolAddress((void**)&h16,    g_h16);
    cudaGetSymbolAddress((void**)&emb16,  g_emb16);
    cudaGetSymbolAddress((void**)&wt1,    g_wt1);
    cudaGetSymbolAddress((void**)&wt2,    g_wt2);
    cudaGetSymbolAddress((void**)&wih16,  g_wih16);
    cudaGetSymbolAddress((void**)&emb,    g_emb);
    cudaGetSymbolAddress((void**)&gsum,   g_gsum);
    cudaGetSymbolAddress((void**)&gcnt,   g_gcnt);
    cudaGetSymbolAddress((void**)&whhT,   g_whhT);
    cudaGetSymbolAddress((void**)&bsum,   g_bsum);
    cudaGetSymbolAddress((void**)&xw,     g_xw);
    cudaGetSymbolAddress((void**)&hl0,    g_hl0);
    cudaGetSymbolAddress((void**)&hl1,    g_hl1);

    cudaFuncSetAttribute(k_gemm_h,  cudaFuncAttributeMaxDynamicSharedMemorySize, HMMA_SMEM);
    cudaFuncSetAttribute(k_gemm_hx, cudaFuncAttributeMaxDynamicSharedMemorySize, HMMA_SMEM);
    cudaFuncSetAttribute(k_lstm_all, cudaFuncAttributeMaxDynamicSharedMemorySize, LSTM_SMEM);

    // Lazily created aux stream + events (resource caching only).
    static cudaStream_t s1 = nullptr;
    static cudaEvent_t ev[2];
    if (!s1) {
        cudaStreamCreate(&s1);
        for (int i = 0; i < 2; i++) cudaEventCreateWithFlags(&ev[i], cudaEventDisableTiming);
    }

    cudaStream_t s = 0;
    cudaMemsetAsync(degI, 0, (size_t)N * sizeof(int), s);
    cudaMemsetAsync(gsum, 0, BB * HH * sizeof(float), s);
    cudaMemsetAsync(gcnt, 0, BB * sizeof(float), s);
    cudaMemsetAsync(bar,  0, sizeof(unsigned), s);

    int frontThreads = N * DD / 2;      // 6.4M, covers E and N too
    k_front<<<(frontThreads + 255) / 256, 256, 0, s>>>(
        (const float2*)x, (__half2*)x16, dst, degI, batch, gcnt, E, N);
    k_scanA <<<SCAN_NB, 256, 0, s>>>(degI, bsums);
    k_scanB <<<1, 256, 0, s>>>(bsums, rowptr);
    k_scanC <<<SCAN_NB, 256, 0, s>>>(degI, bsums, rowptr, cursor);
    k_fill  <<<(E + 255) / 256, 256, 0, s>>>(src, dst, cursor, esrc, E);
    k_prep_all<<<(4 * HH * HH + 255) / 256, 256, 0, s>>>(
        w1l, w1r, w2l, w2r, w_ih, w_hh, b_ih, b_hh, wt1, wt2, wih16, whhT, bsum);

    int gaBlocks = (N + 7) / 8;
    int gmTiles = (N + 127) / 128;

    // layer 1: h16 = relu([mean(x) | x] @ wt1 + b1l)
    k_gather_h<<<gaBlocks, 256, 0, s>>>((const uint4*)x16, rowptr, esrc, (uint4*)agg16, N);
    k_gemm_h<<<gmTiles, 512, HMMA_SMEM, s>>>(agg16, x16, wt1, b1l, h16, nullptr, N, 1);

    // layer 2: emb(+emb16) = [mean(h) | h] @ wt2 + b2l
    k_gather_h<<<gaBlocks, 256, 0, s>>>((const uint4*)h16, rowptr, esrc, (uint4*)agg16, N);
    k_gemm_h<<<gmTiles, 512, HMMA_SMEM, s>>>(agg16, h16, wt2, b2l, emb16, emb, N, 0);

    // fork: pool (s1) || xw gemm (s0, 64 CTAs); JOIN BOTH before the persistent LSTM
    cudaEventRecord(ev[0], s);
    cudaStreamWaitEvent(s1, ev[0], 0);
    k_pool<<<(N + 511) / 512, 256, 0, s1>>>(emb, batch, gsum, N);
    cudaEventRecord(ev[1], s1);

    k_gemm_hx<<<dim3(16, 4), 512, HMMA_SMEM, s>>>(emb16, paths, wih16, bsum, xw, BB * LL);

    cudaStreamWaitEvent(s, ev[1], 0);   // pool done before LSTM occupies the chip
    k_lstm_all<<<dim3(4, 32), 256, LSTM_SMEM, s>>>(xw, whhT, hl0, hl1, bar);

    // fused tail: concat + scorer + reduce (final h in hl0 after t=31)
    k_tail<<<BB, 256, 0, s>>>(gsum, gcnt, hl0, wm1, bm1, wm2, bm2, out);
}